// round 1
// baseline (speedup 1.0000x reference)
#include <cuda_runtime.h>

namespace {

constexpr int B_  = 8;
constexpr int H_  = 64;
constexpr int W_  = 64;
constexpr int C_  = 128;
constexpr int N_  = 9;
constexpr int F_  = 256;

constexpr int BM      = 64;   // pixels per block = one image row
constexpr int BK      = 32;   // channel chunk
constexpr int THREADS = 256;

// Faithful reproduction of the reference's (2,3,3)->(9,2) reshape order:
// flat = [0,0,0,1,1,1,2,2,2, 0,1,2,0,1,2,0,1,2]; row n = (flat[2n], flat[2n+1])
__constant__ int c_iy[9] = {0, 0, 1, 2, 2, 1, 0, 2, 1};
__constant__ int c_ix[9] = {0, 1, 1, 2, 0, 2, 1, 0, 2};

__global__ __launch_bounds__(THREADS)
void deform_conv_kernel(const float* __restrict__ x,
                        const float* __restrict__ offs,
                        const float* __restrict__ Wt,
                        const float* __restrict__ bias,
                        float* __restrict__ out) {
    __shared__ float A_s[BK][BM];      // mapped values, k-major
    __shared__ float W_s[BK][F_];      // weight tile
    __shared__ int   s_y0[BM];
    __shared__ int   s_x0[BM];
    __shared__ float s_fy[BM];
    __shared__ float s_fx[BM];

    const int tid = threadIdx.x;
    const int bh  = blockIdx.x;       // b*H + h
    const int b   = bh >> 6;          // / H_
    const int h   = bh & 63;          // % H_

    // GEMM thread mapping: ty -> 4 pixels, tx -> 16 filters (interleaved f = j*64 + tx*4 + e)
    const int ty = tid >> 4;          // 0..15
    const int tx = tid & 15;          // 0..15

    // Fill thread mapping: fp -> pixel, cg -> 8-channel group
    const int fp = tid & 63;
    const int cg = tid >> 6;          // 0..3

    const float* img    = x + (size_t)b * (H_ * W_ * C_);
    const float* offrow = offs + (size_t)bh * W_ * (2 * N_);

    float acc[4][16];
    #pragma unroll
    for (int i = 0; i < 4; i++)
        #pragma unroll
        for (int j = 0; j < 16; j++) acc[i][j] = 0.0f;

    for (int n = 0; n < N_; n++) {
        // ---- per-tap coordinates (one thread per pixel) ----
        if (tid < BM) {
            const int p = tid;
            float offy = offrow[p * (2 * N_) + 2 * n];
            float offx = offrow[p * (2 * N_) + 2 * n + 1];
            float cy = (float)(h - 1 + c_iy[n]) + offy;
            float cx = (float)(p - 1 + c_ix[n]) + offx;
            cy = fminf(fmaxf(cy, 0.0f), (float)(H_ - 1));
            cx = fminf(fmaxf(cx, 0.0f), (float)(W_ - 1));
            float y0f = floorf(cy);
            float x0f = floorf(cx);
            s_y0[p] = (int)y0f;
            s_x0[p] = (int)x0f;
            s_fy[p] = cy - y0f;
            s_fx[p] = cx - x0f;
        }

        for (int c0 = 0; c0 < C_; c0 += BK) {
            __syncthreads();  // protects A_s/W_s from prior reads + coords visibility

            // ---- stage W tile: Wt[n][c0+kk][f], 32x256 floats, 8 float4/thread ----
            {
                const float* wsrc = Wt + ((size_t)n * C_ + c0) * F_;
                #pragma unroll
                for (int i = 0; i < 8; i++) {
                    int idx = i * THREADS + tid;   // float4 index 0..2047
                    int kk  = idx >> 6;
                    int f4  = idx & 63;
                    float4 v = reinterpret_cast<const float4*>(wsrc + kk * F_)[f4];
                    reinterpret_cast<float4*>(&W_s[kk][0])[f4] = v;
                }
            }

            // ---- stage A tile: bilinear sample 8 channels for pixel fp ----
            {
                const int   y0 = s_y0[fp];
                const int   x0 = s_x0[fp];
                const float fy = s_fy[fp];
                const float fx = s_fx[fp];
                const int   y1 = min(y0 + 1, H_ - 1);
                const int   x1 = min(x0 + 1, W_ - 1);
                const int   cb = c0 + cg * 8;
                const float* p00 = img + ((y0 * W_ + x0) * C_ + cb);  // (y0,x0) = lt
                const float* p10 = img + ((y1 * W_ + x0) * C_ + cb);  // (y1,x0) = rt
                const float* p01 = img + ((y0 * W_ + x1) * C_ + cb);  // (y0,x1) = lb
                const float* p11 = img + ((y1 * W_ + x1) * C_ + cb);  // (y1,x1) = rb
                #pragma unroll
                for (int j = 0; j < 2; j++) {
                    float4 vlt = reinterpret_cast<const float4*>(p00)[j];
                    float4 vrt = reinterpret_cast<const float4*>(p10)[j];
                    float4 vlb = reinterpret_cast<const float4*>(p01)[j];
                    float4 vrb = reinterpret_cast<const float4*>(p11)[j];
                    const int kr = cg * 8 + j * 4;
                    // vals_t = lt + (rt-lt)*fy ; vals_b = lb + (rb-lb)*fy ; m = t + (b-t)*fx
                    {
                        float t0 = vlt.x + (vrt.x - vlt.x) * fy;
                        float b0 = vlb.x + (vrb.x - vlb.x) * fy;
                        A_s[kr + 0][fp] = t0 + (b0 - t0) * fx;
                    }
                    {
                        float t0 = vlt.y + (vrt.y - vlt.y) * fy;
                        float b0 = vlb.y + (vrb.y - vlb.y) * fy;
                        A_s[kr + 1][fp] = t0 + (b0 - t0) * fx;
                    }
                    {
                        float t0 = vlt.z + (vrt.z - vlt.z) * fy;
                        float b0 = vlb.z + (vrb.z - vlb.z) * fy;
                        A_s[kr + 2][fp] = t0 + (b0 - t0) * fx;
                    }
                    {
                        float t0 = vlt.w + (vrt.w - vlt.w) * fy;
                        float b0 = vlb.w + (vrb.w - vlb.w) * fy;
                        A_s[kr + 3][fp] = t0 + (b0 - t0) * fx;
                    }
                }
            }

            __syncthreads();

            // ---- register-tiled GEMM: 4 pixels x 16 filters per thread ----
            #pragma unroll
            for (int kk = 0; kk < BK; kk++) {
                float4 a4 = *reinterpret_cast<const float4*>(&A_s[kk][ty * 4]);
                float a0 = a4.x, a1 = a4.y, a2 = a4.z, a3 = a4.w;
                #pragma unroll
                for (int j = 0; j < 4; j++) {
                    // f = j*64 + tx*4 + e  (bank-conflict-free across tx)
                    float4 w4 = reinterpret_cast<const float4*>(&W_s[kk][0])[j * 16 + tx];
                    acc[0][j * 4 + 0] += a0 * w4.x;
                    acc[0][j * 4 + 1] += a0 * w4.y;
                    acc[0][j * 4 + 2] += a0 * w4.z;
                    acc[0][j * 4 + 3] += a0 * w4.w;
                    acc[1][j * 4 + 0] += a1 * w4.x;
                    acc[1][j * 4 + 1] += a1 * w4.y;
                    acc[1][j * 4 + 2] += a1 * w4.z;
                    acc[1][j * 4 + 3] += a1 * w4.w;
                    acc[2][j * 4 + 0] += a2 * w4.x;
                    acc[2][j * 4 + 1] += a2 * w4.y;
                    acc[2][j * 4 + 2] += a2 * w4.z;
                    acc[2][j * 4 + 3] += a2 * w4.w;
                    acc[3][j * 4 + 0] += a3 * w4.x;
                    acc[3][j * 4 + 1] += a3 * w4.y;
                    acc[3][j * 4 + 2] += a3 * w4.z;
                    acc[3][j * 4 + 3] += a3 * w4.w;
                }
            }
        }
    }

    // ---- epilogue: add bias, write out[bh][p][f] ----
    float* orow = out + (size_t)bh * W_ * F_;
    #pragma unroll
    for (int i = 0; i < 4; i++) {
        const int p = ty * 4 + i;
        #pragma unroll
        for (int j = 0; j < 4; j++) {
            const int f = j * 64 + tx * 4;
            float4 bb = *reinterpret_cast<const float4*>(bias + f);
            float4 o;
            o.x = acc[i][j * 4 + 0] + bb.x;
            o.y = acc[i][j * 4 + 1] + bb.y;
            o.z = acc[i][j * 4 + 2] + bb.z;
            o.w = acc[i][j * 4 + 3] + bb.w;
            *reinterpret_cast<float4*>(orow + p * F_ + f) = o;
        }
    }
}

}  // namespace

extern "C" void kernel_launch(void* const* d_in, const int* in_sizes, int n_in,
                              void* d_out, int out_size) {
    const float* x    = (const float*)d_in[0];   // (8,64,64,128)
    const float* offs = (const float*)d_in[1];   // (8,64,64,18)
    const float* Wt   = (const float*)d_in[2];   // (9,128,256)
    const float* bias = (const float*)d_in[3];   // (256,)
    float* out = (float*)d_out;                  // (8,64,64,256)

    deform_conv_kernel<<<B_ * H_, THREADS>>>(x, offs, Wt, bias, out);
}

// round 3
// speedup vs baseline: 2.9787x; 2.9787x over previous
#include <cuda_runtime.h>
#include <cstdint>

namespace {

constexpr int B_ = 8, H_ = 64, W_ = 64, C_ = 128, N_ = 9, F_ = 256;
constexpr int THREADS = 512;
constexpr int NCHUNK  = N_ * (C_ / 32);   // 36 chunks of K=32
constexpr int PADK    = 36;               // padded k-stride (floats): bank = 4*row+col

// floats offsets in dynamic smem
constexpr int A_OFF   = 0;                 // A_s[128][PADK]
constexpr int W_OFF   = 128 * PADK;        // W_s[256][PADK]
constexpr int CRD_OFF = W_OFF + 256 * PADK;
constexpr int SMEM_FLOATS = CRD_OFF + 4 * 128;
constexpr int SMEM_BYTES  = SMEM_FLOATS * 4;   // 57344

// Faithful reproduction of reference (2,3,3)->(9,2) reshape order
__constant__ int c_iy[9] = {0, 0, 1, 2, 2, 1, 0, 2, 1};
__constant__ int c_ix[9] = {0, 1, 1, 2, 0, 2, 1, 0, 2};

// W transposed + tf32-rounded: [n][f][c]
__device__ uint32_t g_Wt[N_ * F_ * C_];

__device__ __forceinline__ uint32_t f2tf32(float v) {
    uint32_t u;
    asm("cvt.rna.tf32.f32 %0, %1;" : "=r"(u) : "f"(v));
    return u;
}

__device__ __forceinline__ void mma_tf32(float* c, const uint32_t* a, const uint32_t* b) {
    asm volatile(
        "mma.sync.aligned.m16n8k8.row.col.f32.tf32.tf32.f32 "
        "{%0,%1,%2,%3}, {%4,%5,%6,%7}, {%8,%9}, {%0,%1,%2,%3};"
        : "+f"(c[0]), "+f"(c[1]), "+f"(c[2]), "+f"(c[3])
        : "r"(a[0]), "r"(a[1]), "r"(a[2]), "r"(a[3]), "r"(b[0]), "r"(b[1]));
}

// ---------------- W transpose + tf32 round ----------------
__global__ void transpose_w_kernel(const float* __restrict__ Wt) {
    __shared__ float tile[32][33];
    const int n  = blockIdx.z;
    const int ct = blockIdx.y;   // c tile (0..3)
    const int ft = blockIdx.x;   // f tile (0..7)
    const int tx = threadIdx.x & 31;
    const int ty = threadIdx.x >> 5;  // 0..7
    #pragma unroll
    for (int r = 0; r < 4; r++) {
        int c = ct * 32 + ty + r * 8;
        int f = ft * 32 + tx;
        tile[ty + r * 8][tx] = Wt[((size_t)n * C_ + c) * F_ + f];
    }
    __syncthreads();
    #pragma unroll
    for (int r = 0; r < 4; r++) {
        int f = ft * 32 + ty + r * 8;
        int c = ct * 32 + tx;
        g_Wt[((size_t)n * F_ + f) * C_ + c] = f2tf32(tile[tx][ty + r * 8]);
    }
}

// ---------------- main fused kernel ----------------
__global__ __launch_bounds__(THREADS, 1)
void deform_mma_kernel(const float* __restrict__ x,
                       const float* __restrict__ offs,
                       const float* __restrict__ bias,
                       float* __restrict__ out) {
    extern __shared__ float smf[];
    uint32_t* A_s = (uint32_t*)(smf + A_OFF);   // [128][PADK] tf32 bits
    uint32_t* W_s = (uint32_t*)(smf + W_OFF);   // [256][PADK] tf32 bits
    int*   s_y0 = (int*)(smf + CRD_OFF);
    int*   s_x0 = s_y0 + 128;
    float* s_fy = (float*)(s_x0 + 128);
    float* s_fx = s_fy + 128;

    const int tid  = threadIdx.x;
    const int wid  = tid >> 5;
    const int lane = tid & 31;
    const int wr   = wid >> 2;        // warp row (0..3): m base = wr*32
    const int wc   = wid & 3;         // warp col (0..3): f base = wc*64
    const int gq   = lane >> 2;       // groupID
    const int tq   = lane & 3;        // threadID in group

    const int blk = blockIdx.x;
    const int b   = blk >> 5;
    const int h0  = (blk & 31) * 2;
    const float* img = x + (size_t)b * H_ * W_ * C_;

    const int c4  = tid & 7;          // float4 index within 32-ch chunk
    const int pix = tid >> 3;         // 0..63

    float acc[2][8][4];
    #pragma unroll
    for (int mi = 0; mi < 2; mi++)
        #pragma unroll
        for (int ni = 0; ni < 8; ni++)
            #pragma unroll
            for (int r = 0; r < 4; r++) acc[mi][ni][r] = 0.0f;

    for (int it = 0; it < NCHUNK; it++) {
        const int n  = it >> 2;
        const int cc = it & 3;

        __syncthreads();  // previous chunk's MMA reads done; smem reusable

        // ---- per-tap coordinates ----
        if (cc == 0 && tid < 128) {
            const int lp = tid;
            const int hh = h0 + (lp >> 6);
            const int ww = lp & 63;
            const float* orow = offs + (((size_t)(b * H_ + hh) * W_ + ww) * (2 * N_));
            float cy = (float)(hh - 1 + c_iy[n]) + orow[2 * n];
            float cx = (float)(ww - 1 + c_ix[n]) + orow[2 * n + 1];
            cy = fminf(fmaxf(cy, 0.0f), 63.0f);
            cx = fminf(fmaxf(cx, 0.0f), 63.0f);
            float y0f = floorf(cy);
            float x0f = floorf(cx);
            s_y0[lp] = (int)y0f;
            s_x0[lp] = (int)x0f;
            s_fy[lp] = cy - y0f;
            s_fx[lp] = cx - x0f;
        }
        if (cc == 0) __syncthreads();

        // ---- stage A: bilinear sample, tf32 round ----
        {
            const int c_off = cc * 32 + c4 * 4;
            #pragma unroll
            for (int i = 0; i < 2; i++) {
                const int lp = pix + i * 64;
                const int y0 = s_y0[lp];
                const int x0 = s_x0[lp];
                const float fy = s_fy[lp];
                const float fx = s_fx[lp];
                const int y1 = min(y0 + 1, 63);
                const int x1 = min(x0 + 1, 63);
                float4 vlt = *(const float4*)(img + ((y0 * 64 + x0) << 7) + c_off);
                float4 vrt = *(const float4*)(img + ((y1 * 64 + x0) << 7) + c_off);
                float4 vlb = *(const float4*)(img + ((y0 * 64 + x1) << 7) + c_off);
                float4 vrb = *(const float4*)(img + ((y1 * 64 + x1) << 7) + c_off);
                float t0 = vlt.x + (vrt.x - vlt.x) * fy;
                float b0 = vlb.x + (vrb.x - vlb.x) * fy;
                float t1 = vlt.y + (vrt.y - vlt.y) * fy;
                float b1 = vlb.y + (vrb.y - vlb.y) * fy;
                float t2 = vlt.z + (vrt.z - vlt.z) * fy;
                float b2 = vlb.z + (vrb.z - vlb.z) * fy;
                float t3 = vlt.w + (vrt.w - vlt.w) * fy;
                float b3 = vlb.w + (vrb.w - vlb.w) * fy;
                uint4 v;
                v.x = f2tf32(t0 + (b0 - t0) * fx);
                v.y = f2tf32(t1 + (b1 - t1) * fx);
                v.z = f2tf32(t2 + (b2 - t2) * fx);
                v.w = f2tf32(t3 + (b3 - t3) * fx);
                *(uint4*)(A_s + lp * PADK + c4 * 4) = v;
            }
        }

        // ---- stage W: g_Wt[n][f][cc*32 + c4*4 ..] ----
        {
            const uint32_t* wsrc = g_Wt + (size_t)n * F_ * C_ + cc * 32 + c4 * 4;
            const int f0 = pix;   // 0..63
            #pragma unroll
            for (int j = 0; j < 4; j++) {
                const int f = f0 + j * 64;
                uint4 v = *(const uint4*)(wsrc + (size_t)f * C_);
                *(uint4*)(W_s + f * PADK + c4 * 4) = v;
            }
        }

        __syncthreads();

        // ---- MMA: 4 k-steps of m16n8k8 tf32 ----
        #pragma unroll
        for (int kk = 0; kk < 4; kk++) {
            const int kb = kk * 8 + tq;
            uint32_t a[2][4];
            #pragma unroll
            for (int mi = 0; mi < 2; mi++) {
                const int r0 = wr * 32 + mi * 16 + gq;
                a[mi][0] = A_s[r0 * PADK + kb];
                a[mi][1] = A_s[(r0 + 8) * PADK + kb];
                a[mi][2] = A_s[r0 * PADK + kb + 4];
                a[mi][3] = A_s[(r0 + 8) * PADK + kb + 4];
            }
            uint32_t bfr[8][2];
            #pragma unroll
            for (int ni = 0; ni < 8; ni++) {
                const int fr = wc * 64 + ni * 8 + gq;
                bfr[ni][0] = W_s[fr * PADK + kb];
                bfr[ni][1] = W_s[fr * PADK + kb + 4];
            }
            #pragma unroll
            for (int mi = 0; mi < 2; mi++)
                #pragma unroll
                for (int ni = 0; ni < 8; ni++)
                    mma_tf32(acc[mi][ni], a[mi], bfr[ni]);
        }
    }

    // ---- epilogue: add bias, store ----
    #pragma unroll
    for (int mi = 0; mi < 2; mi++) {
        const int row0 = wr * 32 + mi * 16 + gq;
        float* o0 = out + ((size_t)blk * 128 + row0) * F_;
        float* o1 = o0 + 8 * F_;
        #pragma unroll
        for (int ni = 0; ni < 8; ni++) {
            const int f = wc * 64 + ni * 8 + tq * 2;
            const float2 bb = *(const float2*)(bias + f);
            float2 r0, r1;
            r0.x = acc[mi][ni][0] + bb.x;
            r0.y = acc[mi][ni][1] + bb.y;
            r1.x = acc[mi][ni][2] + bb.x;
            r1.y = acc[mi][ni][3] + bb.y;
            *(float2*)(o0 + f) = r0;
            *(float2*)(o1 + f) = r1;
        }
    }
}

}  // namespace

extern "C" void kernel_launch(void* const* d_in, const int* in_sizes, int n_in,
                              void* d_out, int out_size) {
    (void)in_sizes; (void)n_in; (void)out_size;
    const float* x    = (const float*)d_in[0];   // (8,64,64,128)
    const float* offs = (const float*)d_in[1];   // (8,64,64,18)
    const float* Wt   = (const float*)d_in[2];   // (9,128,256)
    const float* bias = (const float*)d_in[3];   // (256,)
    float* out = (float*)d_out;                  // (8,64,64,256)

    cudaFuncSetAttribute(deform_mma_kernel,
                         cudaFuncAttributeMaxDynamicSharedMemorySize, SMEM_BYTES);

    transpose_w_kernel<<<dim3(8, 4, 9), 256>>>(Wt);
    deform_mma_kernel<<<256, THREADS, SMEM_BYTES>>>(x, offs, bias, out);
}